// round 10
// baseline (speedup 1.0000x reference)
#include <cuda_runtime.h>
#include <cuda_bf16.h>
#include <cuda_fp8.h>
#include <stdint.h>

#define NROW 4096
#define DIM  1024
#define NT   256
#define RS8  80          // smem row stride in BYTES (64B data + 16B pad, conflict-free)

// Static device scratch (no runtime allocation allowed).
__device__ unsigned char g_X8[(size_t)NROW * DIM];   // 4 MB normalized embeddings (e4m3)
__device__ float g_SIM[(size_t)NROW * NROW];         // 64 MB similarity matrix
__device__ unsigned char g_cls[NROW];
__device__ float g_rowloss[NROW];

// Monotone fp32 <-> uint32 key (ascending order preserved)
__device__ __forceinline__ unsigned int f2k(float f) {
    unsigned int u = __float_as_uint(f);
    return (u & 0x80000000u) ? ~u : (u | 0x80000000u);
}
__device__ __forceinline__ float k2f(unsigned int k) {
    unsigned int u = (k & 0x80000000u) ? (k & 0x7FFFFFFFu) : ~k;
    return __uint_as_float(u);
}

// ---------------------------------------------------------------------------
// Classes: reference declares int64 targets, but JAX without x64 emits int32.
__global__ __launch_bounds__(1024) void cls_kernel(const int* __restrict__ tgt32) {
    __shared__ int s_any;
    const int t = threadIdx.x;
    if (t == 0) s_any = 0;
    __syncthreads();
    int any = 0;
    for (int j = t; j < NROW / 2; j += 1024)
        any |= (tgt32[2 * j + 1] != 0);
    if (any) atomicOr(&s_any, 1);
    __syncthreads();
    const bool is64 = (s_any == 0);
    for (int i = t; i < NROW; i += 1024)
        g_cls[i] = (unsigned char)(is64 ? tgt32[2 * i] : tgt32[i]);
}

// ---------------------------------------------------------------------------
// Single-pass normalize -> packed e4m3.
__global__ __launch_bounds__(256) void normalize_kernel(const float* __restrict__ emb) {
    const int i = blockIdx.x;
    const int t = threadIdx.x;
    const int lane = t & 31;
    const int wid  = t >> 5;
    __shared__ float s[8];

    float4 v = *(const float4*)(emb + (size_t)i * DIM + t * 4);
    float ss = v.x * v.x + v.y * v.y + v.z * v.z + v.w * v.w;
#pragma unroll
    for (int o = 16; o > 0; o >>= 1) ss += __shfl_xor_sync(0xFFFFFFFFu, ss, o);
    if (lane == 0) s[wid] = ss;
    __syncthreads();
    float tot = 0.f;
#pragma unroll
    for (int w = 0; w < 8; w++) tot += s[w];
    const float norm = fmaxf(sqrtf(tot), 1e-12f);

    unsigned int b0 = __nv_cvt_float_to_fp8(v.x / norm, __NV_SATFINITE, __NV_E4M3);
    unsigned int b1 = __nv_cvt_float_to_fp8(v.y / norm, __NV_SATFINITE, __NV_E4M3);
    unsigned int b2 = __nv_cvt_float_to_fp8(v.z / norm, __NV_SATFINITE, __NV_E4M3);
    unsigned int b3 = __nv_cvt_float_to_fp8(v.w / norm, __NV_SATFINITE, __NV_E4M3);
    *(unsigned int*)(g_X8 + (size_t)i * DIM + t * 4) =
        b0 | (b1 << 8) | (b2 << 16) | (b3 << 24);
}

// ---------------------------------------------------------------------------
// SIM = X * X^T in FP8 e4m3 tensor cores (mma.sync m16n8k32, fp32 accum).
// Symmetric: 528 lower-triangular 128x128 tiles; off-diagonal tiles also store
// their transpose via smem staging (coalesced). K pipeline: 16 stages of K=64,
// cp.async double-buffered.
__device__ __forceinline__ void cp16(unsigned int smem_dst, const void* gsrc) {
    asm volatile("cp.async.cg.shared.global [%0], [%1], 16;\n" :: "r"(smem_dst), "l"(gsrc));
}
__device__ __forceinline__ void cp_commit() { asm volatile("cp.async.commit_group;\n"); }
__device__ __forceinline__ void cp_wait0() { asm volatile("cp.async.wait_group 0;\n"); }

__global__ __launch_bounds__(256) void gemm_kernel() {
    // 40 KB: [sA buf0 | sA buf1 | sB buf0 | sB buf1], each 128*RS8 = 10240 B.
    __shared__ __align__(16) unsigned char sm[4 * 128 * RS8];
    float (*tr)[132] = reinterpret_cast<float (*)[132]>(sm);   // transpose staging

    const int t    = threadIdx.x;
    const int lane = t & 31;
    const int wid  = t >> 5;
    const int wm   = (wid >> 2) * 64;   // warp m offset (0 or 64)
    const int wn   = (wid & 3) * 32;    // warp n offset (0,32,64,96)

    // triangular decode: block b -> (p, q) with p >= q
    const int b = blockIdx.x;
    int p = (int)((sqrtf(8.f * (float)b + 1.f) - 1.f) * 0.5f);
    while ((p + 1) * (p + 2) / 2 <= b) p++;
    while (p * (p + 1) / 2 > b) p--;
    const int q  = b - p * (p + 1) / 2;
    const int bi = p * 128;
    const int bj = q * 128;

    float acc[4][4][4];
#pragma unroll
    for (int mt = 0; mt < 4; mt++)
#pragma unroll
        for (int nt = 0; nt < 4; nt++)
#pragma unroll
            for (int r = 0; r < 4; r++) acc[mt][nt][r] = 0.f;

    const unsigned int smb = (unsigned int)__cvta_generic_to_shared(sm);

    // stage loader: per tile 128 rows x 64B = 512 16B-chunks; A + B.
    auto load_stage = [&](int buf, int s) {
        const unsigned int a_s = smb + buf * (128 * RS8);
        const unsigned int b_s = smb + (2 + buf) * (128 * RS8);
        const unsigned char* gA = g_X8 + (size_t)bi * DIM + s * 64;
        const unsigned char* gB = g_X8 + (size_t)bj * DIM + s * 64;
#pragma unroll
        for (int it = 0; it < 2; it++) {
            const int c   = t + it * 256;
            const int row = c >> 2;
            const int off = (c & 3) * 16;
            cp16(a_s + row * RS8 + off, gA + (size_t)row * DIM + off);
            cp16(b_s + row * RS8 + off, gB + (size_t)row * DIM + off);
        }
        cp_commit();
    };

    load_stage(0, 0);
    cp_wait0();
    __syncthreads();

    for (int s = 0; s < 16; s++) {
        const int cbuf = s & 1;
        if (s + 1 < 16) load_stage((s + 1) & 1, s + 1);

        const unsigned int a_s = smb + cbuf * (128 * RS8);
        const unsigned int b_s = smb + (2 + cbuf) * (128 * RS8);
#pragma unroll
        for (int ks = 0; ks < 2; ks++) {              // two K=32 steps per stage
            unsigned int a[4][4], bb[4][2];
#pragma unroll
            for (int mt = 0; mt < 4; mt++) {
                const unsigned int addr =
                    a_s + (wm + mt * 16 + (lane & 15)) * RS8 + ks * 32 + (lane >> 4) * 16;
                asm volatile("ldmatrix.sync.aligned.m8n8.x4.shared.b16 {%0,%1,%2,%3}, [%4];"
                             : "=r"(a[mt][0]), "=r"(a[mt][1]), "=r"(a[mt][2]), "=r"(a[mt][3])
                             : "r"(addr));
            }
#pragma unroll
            for (int nt = 0; nt < 4; nt++) {
                const unsigned int addr =
                    b_s + (wn + nt * 8 + (lane & 7)) * RS8 + ks * 32 + ((lane >> 3) & 1) * 16;
                asm volatile("ldmatrix.sync.aligned.m8n8.x2.shared.b16 {%0,%1}, [%2];"
                             : "=r"(bb[nt][0]), "=r"(bb[nt][1]) : "r"(addr));
            }
#pragma unroll
            for (int mt = 0; mt < 4; mt++)
#pragma unroll
                for (int nt = 0; nt < 4; nt++) {
                    asm volatile(
                        "mma.sync.aligned.m16n8k32.row.col.f32.e4m3.e4m3.f32 "
                        "{%0,%1,%2,%3},{%4,%5,%6,%7},{%8,%9},{%0,%1,%2,%3};"
                        : "+f"(acc[mt][nt][0]), "+f"(acc[mt][nt][1]),
                          "+f"(acc[mt][nt][2]), "+f"(acc[mt][nt][3])
                        : "r"(a[mt][0]), "r"(a[mt][1]), "r"(a[mt][2]), "r"(a[mt][3]),
                          "r"(bb[nt][0]), "r"(bb[nt][1]));
                }
        }
        if (s + 1 < 16) cp_wait0();
        __syncthreads();
    }

    // ---- direct store of (bi, bj) tile (coalesced) ----
#pragma unroll
    for (int mt = 0; mt < 4; mt++) {
#pragma unroll
        for (int nt = 0; nt < 4; nt++) {
            int r0 = bi + wm + mt * 16 + (lane >> 2);
            int c0 = bj + wn + nt * 8 + (lane & 3) * 2;
            *(float2*)(g_SIM + (size_t)r0 * NROW + c0) =
                make_float2(acc[mt][nt][0], acc[mt][nt][1]);
            *(float2*)(g_SIM + (size_t)(r0 + 8) * NROW + c0) =
                make_float2(acc[mt][nt][2], acc[mt][nt][3]);
        }
    }

    // ---- transposed store of (bj, bi) tile, staged via smem ----
    if (p != q) {
        for (int cc = 0; cc < 4; cc++) {
            __syncthreads();
            if ((wid & 3) == cc) {
#pragma unroll
                for (int mt = 0; mt < 4; mt++)
#pragma unroll
                    for (int nt = 0; nt < 4; nt++) {
                        int r0 = wm + mt * 16 + (lane >> 2);
                        int c0 = nt * 8 + (lane & 3) * 2;
                        tr[c0    ][r0    ] = acc[mt][nt][0];
                        tr[c0 + 1][r0    ] = acc[mt][nt][1];
                        tr[c0    ][r0 + 8] = acc[mt][nt][2];
                        tr[c0 + 1][r0 + 8] = acc[mt][nt][3];
                    }
            }
            __syncthreads();
            const int c = t >> 3;
            const int r = (t & 7) * 16;
            float* dst = g_SIM + (size_t)(bj + cc * 32 + c) * NROW + bi + r;
#pragma unroll
            for (int k = 0; k < 4; k++)
                *(float4*)(dst + k * 4) = *(float4*)(&tr[c][r + k * 4]);
        }
    }
}

// ---------------------------------------------------------------------------
// Per-row loss (R6-proven): pre-masked keys, fused round-0 histogram, round-1,
// candidate shortcut at 16-bit prefix, exact radix fallback.
__global__ __launch_bounds__(NT) void row_loss_kernel() {
    __shared__ unsigned int s_k[NROW];      // 16 KB
    __shared__ float        s_p[NROW];      // 16 KB
    __shared__ unsigned int s_hist[256];
    __shared__ unsigned int s_cand[256];
    __shared__ unsigned int s_wtot[8];
    __shared__ float        s_red[8];
    __shared__ unsigned int sh_sel, sh_r, sh_h, sh_cnt;
    __shared__ unsigned int sh_key, sh_m;

    const int i    = blockIdx.x;
    const int t    = threadIdx.x;
    const int lane = t & 31;
    const int wid  = t >> 5;
    const unsigned char myc = g_cls[i];
    const float* row = g_SIM + (size_t)i * NROW;

    s_hist[t] = 0;
    __syncthreads();

    float pmax = -1e30f;
    int   kneg = 0;
#pragma unroll
    for (int c = 0; c < 4; c++) {
        const int j0 = (c * NT + t) * 4;
        float4 v4 = *(const float4*)(row + j0);
        uchar4 c4 = *(const uchar4*)(g_cls + j0);
        float vv[4] = {v4.x, v4.y, v4.z, v4.w};
        unsigned char cc[4] = {c4.x, c4.y, c4.z, c4.w};
        unsigned int kk[4];
        float        pp[4];
#pragma unroll
        for (int e = 0; e < 4; e++) {
            const int idx = j0 + e;
            if (cc[e] != myc) {
                const unsigned int key = f2k(vv[e]);
                kk[e] = key; pp[e] = -1e30f;
                kneg++;
                atomicAdd(&s_hist[key >> 24], 1u);
            } else {
                kk[e] = 0u;
                pp[e] = (idx != i) ? vv[e] : -1e30f;
                pmax = fmaxf(pmax, pp[e]);
            }
        }
        *(uint4*)(s_k + j0)  = make_uint4(kk[0], kk[1], kk[2], kk[3]);
        *(float4*)(s_p + j0) = make_float4(pp[0], pp[1], pp[2], pp[3]);
    }
#pragma unroll
    for (int o = 16; o > 0; o >>= 1) {
        kneg += __shfl_xor_sync(0xFFFFFFFFu, kneg, o);
        pmax  = fmaxf(pmax, __shfl_xor_sync(0xFFFFFFFFu, pmax, o));
    }
    if (lane == 0) { s_wtot[wid] = (unsigned int)kneg; s_red[wid] = pmax; }
    __syncthreads();
    unsigned int K = 0; float pm = -1e30f;
#pragma unroll
    for (int w = 0; w < 8; w++) { K += s_wtot[w]; pm = fmaxf(pm, s_red[w]); }
    const int drop = max((int)floorf((float)K * 0.05f), 1);
    unsigned int r = (unsigned int)(drop + 1);

    auto select_bucket = [&](unsigned int rr) {
        const unsigned int h = s_hist[t];
        unsigned int suf = h;
#pragma unroll
        for (int o = 1; o < 32; o <<= 1) {
            const unsigned int w = __shfl_down_sync(0xFFFFFFFFu, suf, o);
            if (lane + o < 32) suf += w;
        }
        if (lane == 0) s_wtot[wid] = suf;
        __syncthreads();
#pragma unroll
        for (int w = 0; w < 8; w++) if (w > wid) suf += s_wtot[w];
        if (suf >= rr && (suf - h) < rr) {
            sh_sel = (unsigned int)t;
            sh_r   = rr - (suf - h);
            sh_h   = h;
        }
        __syncthreads();
    };

    select_bucket(r);
    unsigned int prefix = sh_sel;
    r = sh_r;
    __syncthreads();

    s_hist[t] = 0;
    __syncthreads();
#pragma unroll
    for (int c = 0; c < 4; c++) {
        uint4 k4 = *(const uint4*)(s_k + (c * NT + t) * 4);
        unsigned int kk[4] = {k4.x, k4.y, k4.z, k4.w};
#pragma unroll
        for (int e = 0; e < 4; e++)
            if ((kk[e] >> 24) == prefix)
                atomicAdd(&s_hist[(kk[e] >> 16) & 255u], 1u);
    }
    __syncthreads();
    select_bucket(r);
    prefix = (prefix << 8) | sh_sel;
    r = sh_r;
    __syncthreads();

    if (t == 0) sh_cnt = 0;
    __syncthreads();
#pragma unroll
    for (int c = 0; c < 4; c++) {
        uint4 k4 = *(const uint4*)(s_k + (c * NT + t) * 4);
        unsigned int kk[4] = {k4.x, k4.y, k4.z, k4.w};
#pragma unroll
        for (int e = 0; e < 4; e++)
            if ((kk[e] >> 16) == prefix) {
                unsigned int pslot = atomicAdd(&sh_cnt, 1u);
                if (pslot < 256) s_cand[pslot] = kk[e];
            }
    }
    __syncthreads();

    if (sh_cnt <= 256u) {
        const unsigned int C = sh_cnt;
        if (t < (int)C) {
            const unsigned int k = s_cand[t];
            unsigned int cg = 0, ce = 0;
            for (unsigned int j = 0; j < C; j++) {
                const unsigned int kj = s_cand[j];
                cg += (kj > k); ce += (kj == k);
            }
            if (cg < r && r <= cg + ce) {
                sh_key = k;
                sh_m   = ce + 1u - (r - cg);
            }
        }
        __syncthreads();
    } else {
#pragma unroll
        for (int shift = 8; shift >= 0; shift -= 8) {
            s_hist[t] = 0;
            __syncthreads();
#pragma unroll
            for (int c = 0; c < 4; c++) {
                uint4 k4 = *(const uint4*)(s_k + (c * NT + t) * 4);
                unsigned int kk[4] = {k4.x, k4.y, k4.z, k4.w};
#pragma unroll
                for (int e = 0; e < 4; e++)
                    if ((kk[e] >> (shift + 8)) == prefix)
                        atomicAdd(&s_hist[(kk[e] >> shift) & 255u], 1u);
            }
            __syncthreads();
            select_bucket(r);
            prefix = (prefix << 8) | sh_sel;
            r = sh_r;
            if (t == 0 && shift == 0) { sh_key = prefix; sh_m = sh_h + 1u - sh_r; }
            __syncthreads();
        }
    }

    const float T = k2f(sh_key);
    const int   m = (int)sh_m;

    const float thr   = T + 0.1f;
    const float lower = fmaxf(0.6f, pm) - 0.1f;
    float ploss = 0.f, ns = 0.f;
#pragma unroll
    for (int c = 0; c < 4; c++) {
        const int j0 = (c * NT + t) * 4;
        uint4  k4 = *(const uint4*)(s_k + j0);
        float4 p4 = *(const float4*)(s_p + j0);
        unsigned int kk[4] = {k4.x, k4.y, k4.z, k4.w};
        float        pp[4] = {p4.x, p4.y, p4.z, p4.w};
#pragma unroll
        for (int e = 0; e < 4; e++) {
            if (kk[e]) {
                const float v = k2f(kk[e]);
                if (v < T && v > lower) ns += v;
            }
            if (pp[e] > -1e29f && pp[e] < thr) ploss += 1.0f - pp[e];
        }
    }
#pragma unroll
    for (int o = 16; o > 0; o >>= 1) {
        ploss += __shfl_xor_sync(0xFFFFFFFFu, ploss, o);
        ns    += __shfl_xor_sync(0xFFFFFFFFu, ns, o);
    }
    if (lane == 0) { s_red[wid] = ploss; s_wtot[wid] = __float_as_uint(ns); }
    __syncthreads();

    if (t == 0) {
        float pl = 0.f, nss = 0.f;
#pragma unroll
        for (int w = 0; w < 8; w++) { pl += s_red[w]; nss += __uint_as_float(s_wtot[w]); }
        float loss = 0.f;
        if (pm > -1e29f) {
            loss = pl + nss;
            if (T > lower) loss += (float)m * T;
        }
        g_rowloss[i] = loss;
    }
}

// ---------------------------------------------------------------------------
__global__ void finalize_kernel(float* __restrict__ out) {
    __shared__ float s[1024];
    int t = threadIdx.x;
    float a = 0.f;
    for (int j = t; j < NROW; j += 1024) a += g_rowloss[j];
    s[t] = a; __syncthreads();
    for (int o = 512; o > 0; o >>= 1) { if (t < o) s[t] += s[t + o]; __syncthreads(); }
    if (t == 0) out[0] = s[0] / (float)NROW;
}

// ---------------------------------------------------------------------------
extern "C" void kernel_launch(void* const* d_in, const int* in_sizes, int n_in,
                              void* d_out, int out_size) {
    const float* emb   = (const float*)d_in[0];
    const int*   tgt32 = (const int*)d_in[1];
    float* out = (float*)d_out;

    cls_kernel<<<1, 1024>>>(tgt32);
    normalize_kernel<<<NROW, 256>>>(emb);
    gemm_kernel<<<528, 256>>>();
    row_loss_kernel<<<NROW, NT>>>();
    finalize_kernel<<<1, 1024>>>(out);
}